// round 11
// baseline (speedup 1.0000x reference)
#include <cuda_runtime.h>
#include <cuda_bf16.h>
#include <math_constants.h>

// Problem constants
#define B   2
#define NP  8192
#define C   64
#define M   4096     // NP * 0.5
#define K   128
#define H   128
#define R2  0.04f    // 0.2^2
#define BM  (B*M)    // 8192 centers total

// ---------------- scratch (device globals; no allocation allowed) ----------------
__device__ int   g_flags[B*NP];
__device__ int   g_sidx[BM];                 // sorted FPS indices (local 0..NP-1), per cloud
__device__ float g_Y[(size_t)B*NP*H];        // x @ W1[:C] + b1   (8 MB)
__device__ int   g_nbr[(size_t)BM*K];        // neighbor local indices (4 MB)
__device__ int   g_ncnt[BM];

// ---------------- packed f32x2 helpers ----------------
__device__ __forceinline__ unsigned long long pack2f(float lo, float hi) {
    unsigned long long r;
    asm("mov.b64 %0, {%1, %2};" : "=l"(r) : "f"(lo), "f"(hi));
    return r;
}
__device__ __forceinline__ unsigned long long fma2(unsigned long long a,
                                                   unsigned long long b,
                                                   unsigned long long c) {
    unsigned long long d;
    asm("fma.rn.f32x2 %0, %1, %2, %3;" : "=l"(d) : "l"(a), "l"(b), "l"(c));
    return d;
}
__device__ __forceinline__ float2 unpack2f(unsigned long long v) {
    float lo, hi;
    asm("mov.b64 {%0, %1}, %2;" : "=f"(lo), "=f"(hi) : "l"(v));
    return make_float2(lo, hi);
}

// ---------------- K0: zero flags ----------------
__global__ void zero_flags_kernel() {
    int i = blockIdx.x * blockDim.x + threadIdx.x;
    if (i < B*NP) g_flags[i] = 0;
}

// ---------------- K1: farthest point sampling (R6 structure, unchanged) ----------------
#define T_FPS 512
#define PTS   (NP / T_FPS)   // 16 points per thread
#define PRS   (PTS / 2)      // 8 packed pairs
#define NW    (T_FPS / 32)   // 16 warps

__global__ void __launch_bounds__(T_FPS, 1)
fps_kernel(const float* __restrict__ pos) {
    const int b   = blockIdx.x;
    const int tid = threadIdx.x;
    const int lane = tid & 31, wid = tid >> 5;

    extern __shared__ float4 sp[];       // 8192 x float4 = 128KB
    __shared__ unsigned long long s_vi[2][NW];   // (value<<32)|idx, parity-buffered

    const float* pb = pos + (size_t)b * NP * 3;
    for (int i = tid; i < NP; i += T_FPS)
        sp[i] = make_float4(pb[i*3+0], pb[i*3+1], pb[i*3+2], 0.0f);
    if (tid == 0) g_flags[b*NP + 0] = 1;   // idx[0] = 0
    __syncthreads();

    // thread-local points, packed 2 per 64-bit register (original index order)
    unsigned long long px2[PRS], py2[PRS], pz2[PRS];
    float mind[PTS];
    const int base = tid * PTS;
    #pragma unroll
    for (int k = 0; k < PRS; k++) {
        float4 a = sp[base + 2*k], q = sp[base + 2*k + 1];
        px2[k] = pack2f(a.x, q.x);
        py2[k] = pack2f(a.y, q.y);
        pz2[k] = pack2f(a.z, q.z);
    }
    #pragma unroll
    for (int k = 0; k < PTS; k++) mind[k] = CUDART_INF_F;

    float4 w0 = sp[0];
    float fx = w0.x, fy = w0.y, fz = w0.z;

    for (int it = 1; it < M; it++) {
        const int cur = it & 1;

        // ---- local: d = (p-f)^2 in f32x2; track (max value, first index) ----
        const unsigned long long nfx2 = pack2f(-fx, -fx);
        const unsigned long long nfy2 = pack2f(-fy, -fy);
        const unsigned long long nfz2 = pack2f(-fz, -fz);
        float bv = 0.0f; int bloc = 0;
        #pragma unroll
        for (int k = 0; k < PRS; k++) {
            unsigned long long dx, dy, dz;
            asm("add.rn.f32x2 %0, %1, %2;" : "=l"(dx) : "l"(px2[k]), "l"(nfx2));
            asm("add.rn.f32x2 %0, %1, %2;" : "=l"(dy) : "l"(py2[k]), "l"(nfy2));
            asm("add.rn.f32x2 %0, %1, %2;" : "=l"(dz) : "l"(pz2[k]), "l"(nfz2));
            unsigned long long d;
            asm("mul.rn.f32x2 %0, %1, %2;" : "=l"(d) : "l"(dz), "l"(dz));
            d = fma2(dy, dy, d);
            d = fma2(dx, dx, d);
            float2 df = unpack2f(d);
            float m0 = fminf(mind[2*k+0], df.x); mind[2*k+0] = m0;
            float m1 = fminf(mind[2*k+1], df.y); mind[2*k+1] = m1;
            if (m0 > bv) { bv = m0; bloc = base + 2*k;     }  // strict >: first max wins
            if (m1 > bv) { bv = m1; bloc = base + 2*k + 1; }
        }

        // ---- warp stage: max value + min index achieving it (pre-barrier) ----
        const unsigned bvu  = __float_as_uint(bv);   // d>=0 -> bits monotone
        const unsigned wmax = __reduce_max_sync(0xffffffffu, bvu);
        const int cand = (bvu == wmax) ? bloc : 0x7fffffff;
        const int wloc = __reduce_min_sync(0xffffffffu, cand);
        if (lane == 0)
            s_vi[cur][wid] = ((unsigned long long)wmax << 32) | (unsigned)wloc;
        __syncthreads();   // single barrier; slots parity-buffered

        // ---- block stage: every warp reduces all 16 warp results itself ----
        const unsigned long long pv = s_vi[cur][lane & (NW-1)];
        const unsigned hv = (unsigned)(pv >> 32);
        const unsigned g  = __reduce_max_sync(0xffffffffu, hv);
        const int ic   = (hv == g) ? (int)(unsigned)pv : 0x7fffffff;
        const int widx = __reduce_min_sync(0xffffffffu, ic);

        const float4 w = sp[widx];
        fx = w.x; fy = w.y; fz = w.z;
        if (tid == 0) g_flags[b*NP + widx] = 1;
    }
}

// ---------------- K2: compaction of flags -> sorted sample indices ----------------
__global__ void compact_kernel() {   // grid = B, block = 32
    const int b = blockIdx.x, lane = threadIdx.x;
    int carry = 0;
    for (int base = 0; base < NP; base += 32) {
        int f = g_flags[b*NP + base + lane];
        unsigned m = __ballot_sync(0xffffffffu, f);
        if (f) {
            int r = __popc(m & ((1u << lane) - 1u));
            g_sidx[b*M + carry + r] = base + lane;
        }
        carry += __popc(m);
    }
}

// ---------------- K3: Y = x @ W1[:C] + b1 (split for profiler slotting) ----------------
__global__ void ymat_kernel(const float* __restrict__ x,
                            const float* __restrict__ W1,
                            const float* __restrict__ b1,
                            int p0) {
    const int p = p0 + blockIdx.x;   // point id
    const int h = threadIdx.x;       // 0 .. H-1
    __shared__ float xv[C];
    if (h < C) xv[h] = x[(size_t)p*C + h];
    __syncthreads();
    float acc = b1[h];
    #pragma unroll
    for (int c = 0; c < C; c++)
        acc = fmaf(xv[c], W1[c*H + h], acc);
    g_Y[(size_t)p*H + h] = acc;
}

// ---------------- K4: radius / top-K neighbor selection ----------------
#define CAP 2048
__global__ void radius_kernel(const float* __restrict__ pos) {  // grid = BM, block = 256
    const int ctr = blockIdx.x;
    const int b   = ctr / M;
    const int ci  = g_sidx[ctr];
    const float* pb = pos + (size_t)b * NP * 3;
    const float cx = pb[ci*3+0], cy = pb[ci*3+1], cz = pb[ci*3+2];

    __shared__ float cd[CAP];
    __shared__ int   cidx[CAP];
    __shared__ int   cnt;
    if (threadIdx.x == 0) cnt = 0;
    __syncthreads();

    for (int i = threadIdx.x; i < NP; i += 256) {
        float dx = pb[i*3+0] - cx, dy = pb[i*3+1] - cy, dz = pb[i*3+2] - cz;
        float d  = fmaf(dx, dx, fmaf(dy, dy, dz*dz));
        if (d <= R2) {
            int s = atomicAdd(&cnt, 1);
            if (s < CAP) { cd[s] = d; cidx[s] = i; }
        }
    }
    __syncthreads();
    int n = min(cnt, CAP);
    if (n <= K) {
        for (int c = threadIdx.x; c < n; c += 256)
            g_nbr[(size_t)ctr*K + c] = cidx[c];
        if (threadIdx.x == 0) g_ncnt[ctr] = n;
    } else {
        // rank selection: keep the K lexicographically-smallest (d2, idx) pairs.
        for (int c = threadIdx.x; c < n; c += 256) {
            float d = cd[c]; int id = cidx[c];
            int r = 0;
            for (int j = 0; j < n; j++) {
                float dj = cd[j];
                r += (dj < d) || (dj == d && cidx[j] < id);
            }
            if (r < K) g_nbr[(size_t)ctr*K + r] = id;
        }
        if (threadIdx.x == 0) g_ncnt[ctr] = K;
    }
}

// ---------------- K5: PointNetConv (f32x2 matmul, 4 neighbors per barrier) ----------------
#define GRP 4
__global__ void __launch_bounds__(128, 2)
conv_kernel(const float* __restrict__ pos,
            const float* __restrict__ W1,
            const float* __restrict__ W2,
            const float* __restrict__ b2,
            float* __restrict__ out) {      // grid = BM, block = 128
    const int ctr = blockIdx.x;
    const int b   = ctr / M;
    const int o   = threadIdx.x;

    unsigned long long wreg[H/2];
    #pragma unroll
    for (int k = 0; k < H; k += 2)
        wreg[k >> 1] = pack2f(W2[k*H + o], W2[(k+1)*H + o]);

    const int ci = g_sidx[ctr];
    const float* pb = pos + (size_t)b * NP * 3;
    const float cx = pb[ci*3+0], cy = pb[ci*3+1], cz = pb[ci*3+2];
    const float v0 = W1[(C+0)*H + o], v1 = W1[(C+1)*H + o], v2 = W1[(C+2)*H + o];
    const float bias2 = b2[o];

    const int n = g_ncnt[ctr];
    const int* nb = &g_nbr[(size_t)ctr*K];
    __shared__ __align__(16) float h1[2][GRP][H];

    float omax = 0.0f;

    float yv[GRP], pjx[GRP], pjy[GRP], pjz[GRP];
    #pragma unroll
    for (int g = 0; g < GRP; g++) {
        if (g < n) {
            int j = nb[g];
            yv[g]  = g_Y[(size_t)(b*NP + j)*H + o];
            pjx[g] = pb[j*3+0]; pjy[g] = pb[j*3+1]; pjz[g] = pb[j*3+2];
        }
    }

    for (int g0 = 0; g0 < n; g0 += GRP) {
        const int buf = (g0 >> 2) & 1;
        #pragma unroll
        for (int g = 0; g < GRP; g++) {
            if (g0 + g < n) {
                float hh = yv[g];
                hh = fmaf(pjx[g] - cx, v0, hh);
                hh = fmaf(pjy[g] - cy, v1, hh);
                hh = fmaf(pjz[g] - cz, v2, hh);
                h1[buf][g][o] = fmaxf(hh, 0.0f);
            }
        }
        #pragma unroll
        for (int g = 0; g < GRP; g++) {
            if (g0 + GRP + g < n) {
                int j = nb[g0 + GRP + g];
                yv[g]  = g_Y[(size_t)(b*NP + j)*H + o];
                pjx[g] = pb[j*3+0]; pjy[g] = pb[j*3+1]; pjz[g] = pb[j*3+2];
            }
        }
        __syncthreads();

        #pragma unroll
        for (int g = 0; g < GRP; g++) {
            if (g0 + g < n) {
                const ulonglong2* hp = (const ulonglong2*)&h1[buf][g][0];
                unsigned long long a0 = 0ull, a1 = 0ull, a2 = 0ull, a3 = 0ull;
                #pragma unroll
                for (int q = 0; q < H/4; q += 2) {
                    ulonglong2 hv = hp[q];
                    a0 = fma2(hv.x, wreg[2*q + 0], a0);
                    a1 = fma2(hv.y, wreg[2*q + 1], a1);
                    ulonglong2 hw = hp[q + 1];
                    a2 = fma2(hw.x, wreg[2*q + 2], a2);
                    a3 = fma2(hw.y, wreg[2*q + 3], a3);
                }
                float2 f0 = unpack2f(a0), f1 = unpack2f(a1);
                float2 f2 = unpack2f(a2), f3 = unpack2f(a3);
                float s = ((f0.x + f0.y) + (f1.x + f1.y)) + ((f2.x + f2.y) + (f3.x + f3.y));
                omax = fmaxf(omax, fmaxf(s + bias2, 0.0f));
            }
        }
    }
    out[(size_t)ctr*H + o] = (n > 0) ? omax : 0.0f;
}

// ---------------- K6: pack auxiliary outputs (qpos, batch) if expected ----------------
__global__ void pack_kernel(const float* __restrict__ pos, float* __restrict__ out,
                            int out_size) {
    const int i = blockIdx.x * blockDim.x + threadIdx.x;
    if (i >= BM) return;
    const int b  = i / M;
    const int ci = g_sidx[i];
    const float* pb = pos + (size_t)b * NP * 3;
    const int base_q = BM * H;
    if (out_size >= base_q + BM*3) {
        out[base_q + i*3 + 0] = pb[ci*3+0];
        out[base_q + i*3 + 1] = pb[ci*3+1];
        out[base_q + i*3 + 2] = pb[ci*3+2];
    }
    const int base_b = base_q + BM*3;
    if (out_size >= base_b + BM) {
        out[base_b + i] = (float)b;
    }
}

// ---------------- launch ----------------
extern "C" void kernel_launch(void* const* d_in, const int* in_sizes, int n_in,
                              void* d_out, int out_size) {
    const float* x    = (const float*)d_in[0];
    const float* pos  = (const float*)d_in[1];
    const float* W1   = (const float*)d_in[3];
    const float* b1   = (const float*)d_in[4];
    const float* W2   = (const float*)d_in[5];
    const float* b2   = (const float*)d_in[6];
    float* out = (float*)d_out;

    const int fps_smem = NP * (int)sizeof(float4);   // 128KB float4 pos cache
    cudaFuncSetAttribute(fps_kernel, cudaFuncAttributeMaxDynamicSharedMemorySize, fps_smem);

    // MEASUREMENT ROUND: fps_kernel launched TWICE (second run is idempotent —
    // identical inputs produce the identical selection sequence and re-set the
    // same g_flags bits). T_fps = dur_this_round - 3620us.
    zero_flags_kernel<<<(B*NP + 255)/256, 256>>>();
    ymat_kernel<<<B*NP/2, H>>>(x, W1, b1, 0);
    ymat_kernel<<<B*NP/2, H>>>(x, W1, b1, B*NP/2);
    fps_kernel<<<B, T_FPS, fps_smem>>>(pos);
    fps_kernel<<<B, T_FPS, fps_smem>>>(pos);
    compact_kernel<<<B, 32>>>();
    radius_kernel<<<BM, 256>>>(pos);
    conv_kernel<<<BM, H>>>(pos, W1, W2, b2, out);
    pack_kernel<<<(BM + 255)/256, 256>>>(pos, out, out_size);
}

// round 13
// speedup vs baseline: 1.1273x; 1.1273x over previous
#include <cuda_runtime.h>
#include <cuda_bf16.h>
#include <math_constants.h>
#include <cstdint>

// Problem constants
#define B   2
#define NP  8192
#define C   64
#define M   4096     // NP * 0.5
#define K   128
#define H   128
#define R2  0.04f    // 0.2^2
#define BM  (B*M)    // 8192 centers total

// ---------------- scratch (device globals; no allocation allowed) ----------------
__device__ int   g_flags[B*NP];
__device__ int   g_sidx[BM];                 // sorted FPS indices per cloud
__device__ float g_Y[(size_t)B*NP*H];        // x @ W1[:C] + b1   (8 MB)
__device__ int   g_nbr[(size_t)BM*K];        // neighbor local indices (4 MB)
__device__ int   g_ncnt[BM];

// ---------------- helpers ----------------
__device__ __forceinline__ uint32_t smem_u32(const void* p) {
    uint32_t a;
    asm("{ .reg .u64 t; cvta.to.shared.u64 t, %1; cvt.u32.u64 %0, t; }" : "=r"(a) : "l"(p));
    return a;
}
__device__ __forceinline__ unsigned long long pack2f(float lo, float hi) {
    unsigned long long r;
    asm("mov.b64 %0, {%1, %2};" : "=l"(r) : "f"(lo), "f"(hi));
    return r;
}
__device__ __forceinline__ unsigned long long fma2(unsigned long long a,
                                                   unsigned long long b,
                                                   unsigned long long c) {
    unsigned long long d;
    asm("fma.rn.f32x2 %0, %1, %2, %3;" : "=l"(d) : "l"(a), "l"(b), "l"(c));
    return d;
}
__device__ __forceinline__ float2 unpack2f(unsigned long long v) {
    float lo, hi;
    asm("mov.b64 {%0, %1}, %2;" : "=f"(lo), "=f"(hi) : "l"(v));
    return make_float2(lo, hi);
}

// ---------------- K0: zero flags ----------------
__global__ void zero_flags_kernel() {
    int i = blockIdx.x * blockDim.x + threadIdx.x;
    if (i < B*NP) g_flags[i] = 0;
}

// ---------------- K1: cluster-parallel FPS ----------------
// 8 CTAs per cloud (cluster), 256 threads, 4 points per thread.
// Per iteration: warp-level reduce -> DSMEM all-to-all broadcast of 64 warp
// results -> one mbarrier parity wait (HW sleep) -> every warp reduces 64 slots.
#define FPS_CTAS 8                    // cluster size (portable max)
#define FPS_THR  256
#define FPS_WPB  (FPS_THR/32)         // 8 warps per CTA
#define FPS_PTS  4                    // points per thread (8*256*4 = 8192)
#define NSLOT    (FPS_CTAS*FPS_WPB)   // 64 warp-result slots

__global__ void __launch_bounds__(FPS_THR, 1)
fps_cluster_kernel(const float* __restrict__ pos) {
    uint32_t crank;
    asm("mov.u32 %0, %%cluster_ctarank;" : "=r"(crank));
    const int b    = blockIdx.x / FPS_CTAS;
    const int tid  = threadIdx.x;
    const int lane = tid & 31, wid = tid >> 5;

    extern __shared__ float4 sp[];    // full pos cache per CTA (128KB)
    __shared__ __align__(8) unsigned long long slots[2][NSLOT];
    __shared__ __align__(8) unsigned long long mbar;

    const float* pb = pos + (size_t)b * NP * 3;
    for (int i = tid; i < NP; i += FPS_THR)
        sp[i] = make_float4(pb[i*3+0], pb[i*3+1], pb[i*3+2], 0.0f);
    if (tid == 0) {
        if (crank == 0) g_flags[b*NP + 0] = 1;     // idx[0] = 0
        asm volatile("mbarrier.init.shared.b64 [%0], %1;"
                     :: "r"(smem_u32(&mbar)), "r"((uint32_t)NSLOT) : "memory");
    }
    __syncthreads();
    // all CTAs' mbarriers initialized before anyone arrives
    asm volatile("barrier.cluster.arrive.aligned;" ::: "memory");
    asm volatile("barrier.cluster.wait.aligned;"   ::: "memory");

    // this thread's 4 contiguous points
    float px[FPS_PTS], py[FPS_PTS], pz[FPS_PTS], mind[FPS_PTS];
    const int base = (int)crank * 1024 + tid * FPS_PTS;
    #pragma unroll
    for (int k = 0; k < FPS_PTS; k++) {
        float4 q = sp[base + k];
        px[k] = q.x; py[k] = q.y; pz[k] = q.z;
        mind[k] = CUDART_INF_F;
    }

    const uint32_t mbar_a   = smem_u32(&mbar);
    const uint32_t slot_a0  = smem_u32(&slots[0][crank*FPS_WPB + wid]);
    const uint32_t phase_sz = NSLOT * 8;   // bytes between the two phase buffers

    float4 w0 = sp[0];
    float fx = w0.x, fy = w0.y, fz = w0.z;

    for (int it = 1; it < M; it++) {
        const uint32_t ph = (uint32_t)(it - 1) & 1u;

        // ---- local scan (identical arithmetic to all prior passing rounds) ----
        float bv = 0.0f; int bloc = 0;
        #pragma unroll
        for (int k = 0; k < FPS_PTS; k++) {
            float dx = px[k]-fx, dy = py[k]-fy, dz = pz[k]-fz;
            float d  = fmaf(dx,dx,fmaf(dy,dy,dz*dz));
            float m  = fminf(mind[k], d);
            mind[k] = m;
            if (m > bv) { bv = m; bloc = base + k; }   // strict >: first max wins
        }

        // ---- warp stage: (max value, min index achieving it) ----
        const unsigned bvu  = __float_as_uint(bv);     // d >= 0 -> bits monotone
        const unsigned wmax = __reduce_max_sync(0xffffffffu, bvu);
        const unsigned cand = (bvu == wmax) ? (unsigned)bloc : 0xffffffffu;
        const unsigned wloc = __reduce_min_sync(0xffffffffu, cand);
        const unsigned long long packed =
            ((unsigned long long)wmax << 32) | wloc;

        // ---- broadcast this warp's result to all 8 CTAs + arrive ----
        if (lane < FPS_CTAS) {
            uint32_t rem, rbar;
            const uint32_t slot_local = slot_a0 + ph * phase_sz;
            asm("mapa.shared::cluster.u32 %0, %1, %2;"
                : "=r"(rem) : "r"(slot_local), "r"(lane));
            asm volatile("st.shared::cluster.u64 [%0], %1;"
                         :: "r"(rem), "l"(packed) : "memory");
            asm("mapa.shared::cluster.u32 %0, %1, %2;"
                : "=r"(rbar) : "r"(mbar_a), "r"(lane));
            asm volatile("mbarrier.arrive.release.cluster.shared::cluster.b64 _, [%0];"
                         :: "r"(rbar) : "memory");
        }

        // ---- wait for all 64 arrivals of this phase (HW-sleep wait) ----
        {
            uint32_t done;
            asm volatile(
                "{\n\t.reg .pred p;\n\t"
                "mbarrier.try_wait.parity.acquire.cluster.shared::cta.b64 p, [%1], %2, 0x989680;\n\t"
                "selp.b32 %0, 1, 0, p;\n\t}"
                : "=r"(done) : "r"(mbar_a), "r"(ph) : "memory");
            if (!done) {
                asm volatile(
                    "{\n\t.reg .pred P1;\n\t"
                    "WAIT_LOOP_%=:\n\t"
                    "mbarrier.try_wait.parity.acquire.cluster.shared::cta.b64 P1, [%0], %1, 0x989680;\n\t"
                    "@P1 bra.uni WAIT_DONE_%=;\n\t"
                    "bra.uni WAIT_LOOP_%=;\n\t"
                    "WAIT_DONE_%=:\n\t}"
                    :: "r"(mbar_a), "r"(ph) : "memory");
            }
        }

        // ---- every warp reduces the 64 slots itself (2 per lane) ----
        const unsigned long long a = slots[ph][lane];
        const unsigned long long c = slots[ph][lane + 32];
        const unsigned va = (unsigned)(a >> 32), vc = (unsigned)(c >> 32);
        const unsigned vm = va > vc ? va : vc;
        const unsigned g  = __reduce_max_sync(0xffffffffu, vm);
        unsigned ic = 0xffffffffu;
        if (va == g) ic = (unsigned)a;
        if (vc == g) { unsigned t = (unsigned)c; if (t < ic) ic = t; }
        const unsigned widx = __reduce_min_sync(0xffffffffu, ic);

        const float4 w = sp[widx];
        fx = w.x; fy = w.y; fz = w.z;
        if (crank == 0 && tid == 0) g_flags[b*NP + widx] = 1;
    }
}

// ---------------- K2: compaction of flags -> sorted sample indices ----------------
__global__ void compact_kernel() {   // grid = B, block = 32
    const int b = blockIdx.x, lane = threadIdx.x;
    int carry = 0;
    for (int base = 0; base < NP; base += 32) {
        int f = g_flags[b*NP + base + lane];
        unsigned m = __ballot_sync(0xffffffffu, f);
        if (f) {
            int r = __popc(m & ((1u << lane) - 1u));
            g_sidx[b*M + carry + r] = base + lane;
        }
        carry += __popc(m);
    }
}

// ---------------- K3: Y = x @ W1[:C] + b1 ----------------
__global__ void ymat_kernel(const float* __restrict__ x,
                            const float* __restrict__ W1,
                            const float* __restrict__ b1,
                            int p0) {
    const int p = p0 + blockIdx.x;
    const int h = threadIdx.x;
    __shared__ float xv[C];
    if (h < C) xv[h] = x[(size_t)p*C + h];
    __syncthreads();
    float acc = b1[h];
    #pragma unroll
    for (int c = 0; c < C; c++)
        acc = fmaf(xv[c], W1[c*H + h], acc);
    g_Y[(size_t)p*H + h] = acc;
}

// ---------------- K4: radius / top-K neighbor selection ----------------
#define CAP 2048
__global__ void radius_kernel(const float* __restrict__ pos) {  // grid = BM, block = 256
    const int ctr = blockIdx.x;
    const int b   = ctr / M;
    const int ci  = g_sidx[ctr];
    const float* pb = pos + (size_t)b * NP * 3;
    const float cx = pb[ci*3+0], cy = pb[ci*3+1], cz = pb[ci*3+2];

    __shared__ float cd[CAP];
    __shared__ int   cidx[CAP];
    __shared__ int   cnt;
    if (threadIdx.x == 0) cnt = 0;
    __syncthreads();

    for (int i = threadIdx.x; i < NP; i += 256) {
        float dx = pb[i*3+0] - cx, dy = pb[i*3+1] - cy, dz = pb[i*3+2] - cz;
        float d  = fmaf(dx, dx, fmaf(dy, dy, dz*dz));
        if (d <= R2) {
            int s = atomicAdd(&cnt, 1);
            if (s < CAP) { cd[s] = d; cidx[s] = i; }
        }
    }
    __syncthreads();
    int n = min(cnt, CAP);
    if (n <= K) {
        for (int c = threadIdx.x; c < n; c += 256)
            g_nbr[(size_t)ctr*K + c] = cidx[c];
        if (threadIdx.x == 0) g_ncnt[ctr] = n;
    } else {
        // rank selection: keep the K lexicographically-smallest (d2, idx) pairs.
        for (int c = threadIdx.x; c < n; c += 256) {
            float d = cd[c]; int id = cidx[c];
            int r = 0;
            for (int j = 0; j < n; j++) {
                float dj = cd[j];
                r += (dj < d) || (dj == d && cidx[j] < id);
            }
            if (r < K) g_nbr[(size_t)ctr*K + r] = id;
        }
        if (threadIdx.x == 0) g_ncnt[ctr] = K;
    }
}

// ---------------- K5: PointNetConv ----------------
#define GRP 4
__global__ void __launch_bounds__(128, 2)
conv_kernel(const float* __restrict__ pos,
            const float* __restrict__ W1,
            const float* __restrict__ W2,
            const float* __restrict__ b2,
            float* __restrict__ out) {      // grid = BM, block = 128
    const int ctr = blockIdx.x;
    const int b   = ctr / M;
    const int o   = threadIdx.x;

    unsigned long long wreg[H/2];
    #pragma unroll
    for (int k = 0; k < H; k += 2)
        wreg[k >> 1] = pack2f(W2[k*H + o], W2[(k+1)*H + o]);

    const int ci = g_sidx[ctr];
    const float* pb = pos + (size_t)b * NP * 3;
    const float cx = pb[ci*3+0], cy = pb[ci*3+1], cz = pb[ci*3+2];
    const float v0 = W1[(C+0)*H + o], v1 = W1[(C+1)*H + o], v2 = W1[(C+2)*H + o];
    const float bias2 = b2[o];

    const int n = g_ncnt[ctr];
    const int* nb = &g_nbr[(size_t)ctr*K];
    __shared__ __align__(16) float h1[2][GRP][H];

    float omax = 0.0f;

    float yv[GRP], pjx[GRP], pjy[GRP], pjz[GRP];
    #pragma unroll
    for (int g = 0; g < GRP; g++) {
        if (g < n) {
            int j = nb[g];
            yv[g]  = g_Y[(size_t)(b*NP + j)*H + o];
            pjx[g] = pb[j*3+0]; pjy[g] = pb[j*3+1]; pjz[g] = pb[j*3+2];
        }
    }

    for (int g0 = 0; g0 < n; g0 += GRP) {
        const int buf = (g0 >> 2) & 1;
        #pragma unroll
        for (int g = 0; g < GRP; g++) {
            if (g0 + g < n) {
                float hh = yv[g];
                hh = fmaf(pjx[g] - cx, v0, hh);
                hh = fmaf(pjy[g] - cy, v1, hh);
                hh = fmaf(pjz[g] - cz, v2, hh);
                h1[buf][g][o] = fmaxf(hh, 0.0f);
            }
        }
        #pragma unroll
        for (int g = 0; g < GRP; g++) {
            if (g0 + GRP + g < n) {
                int j = nb[g0 + GRP + g];
                yv[g]  = g_Y[(size_t)(b*NP + j)*H + o];
                pjx[g] = pb[j*3+0]; pjy[g] = pb[j*3+1]; pjz[g] = pb[j*3+2];
            }
        }
        __syncthreads();

        #pragma unroll
        for (int g = 0; g < GRP; g++) {
            if (g0 + g < n) {
                const ulonglong2* hp = (const ulonglong2*)&h1[buf][g][0];
                unsigned long long a0 = 0ull, a1 = 0ull, a2 = 0ull, a3 = 0ull;
                #pragma unroll
                for (int q = 0; q < H/4; q += 2) {
                    ulonglong2 hv = hp[q];
                    a0 = fma2(hv.x, wreg[2*q + 0], a0);
                    a1 = fma2(hv.y, wreg[2*q + 1], a1);
                    ulonglong2 hw = hp[q + 1];
                    a2 = fma2(hw.x, wreg[2*q + 2], a2);
                    a3 = fma2(hw.y, wreg[2*q + 3], a3);
                }
                float2 f0 = unpack2f(a0), f1 = unpack2f(a1);
                float2 f2 = unpack2f(a2), f3 = unpack2f(a3);
                float s = ((f0.x + f0.y) + (f1.x + f1.y)) + ((f2.x + f2.y) + (f3.x + f3.y));
                omax = fmaxf(omax, fmaxf(s + bias2, 0.0f));
            }
        }
    }
    out[(size_t)ctr*H + o] = (n > 0) ? omax : 0.0f;
}

// ---------------- K6: pack auxiliary outputs (qpos, batch) if expected ----------------
__global__ void pack_kernel(const float* __restrict__ pos, float* __restrict__ out,
                            int out_size) {
    const int i = blockIdx.x * blockDim.x + threadIdx.x;
    if (i >= BM) return;
    const int b  = i / M;
    const int ci = g_sidx[i];
    const float* pb = pos + (size_t)b * NP * 3;
    const int base_q = BM * H;
    if (out_size >= base_q + BM*3) {
        out[base_q + i*3 + 0] = pb[ci*3+0];
        out[base_q + i*3 + 1] = pb[ci*3+1];
        out[base_q + i*3 + 2] = pb[ci*3+2];
    }
    const int base_b = base_q + BM*3;
    if (out_size >= base_b + BM) {
        out[base_b + i] = (float)b;
    }
}

// ---------------- launch ----------------
extern "C" void kernel_launch(void* const* d_in, const int* in_sizes, int n_in,
                              void* d_out, int out_size) {
    const float* x    = (const float*)d_in[0];
    const float* pos  = (const float*)d_in[1];
    const float* W1   = (const float*)d_in[3];
    const float* b1   = (const float*)d_in[4];
    const float* W2   = (const float*)d_in[5];
    const float* b2   = (const float*)d_in[6];
    float* out = (float*)d_out;

    const int fps_smem = NP * (int)sizeof(float4);   // 128KB float4 pos cache per CTA
    cudaFuncSetAttribute(fps_cluster_kernel,
                         cudaFuncAttributeMaxDynamicSharedMemorySize, fps_smem);

    zero_flags_kernel<<<(B*NP + 255)/256, 256>>>();
    ymat_kernel<<<B*NP/2, H>>>(x, W1, b1, 0);
    ymat_kernel<<<B*NP/2, H>>>(x, W1, b1, B*NP/2);

    // cluster-parallel FPS: 2 clouds x 8-CTA clusters
    {
        cudaLaunchConfig_t cfg = {};
        cfg.gridDim  = dim3(B * FPS_CTAS, 1, 1);
        cfg.blockDim = dim3(FPS_THR, 1, 1);
        cfg.dynamicSmemBytes = fps_smem;
        cudaLaunchAttribute attrs[1];
        attrs[0].id = cudaLaunchAttributeClusterDimension;
        attrs[0].val.clusterDim.x = FPS_CTAS;
        attrs[0].val.clusterDim.y = 1;
        attrs[0].val.clusterDim.z = 1;
        cfg.attrs = attrs;
        cfg.numAttrs = 1;
        cudaLaunchKernelEx(&cfg, fps_cluster_kernel, pos);
    }

    compact_kernel<<<B, 32>>>();
    radius_kernel<<<BM, 256>>>(pos);
    conv_kernel<<<BM, H>>>(pos, W1, W2, b2, out);
    pack_kernel<<<(BM + 255)/256, 256>>>(pos, out, out_size);
}

// round 17
// speedup vs baseline: 1.6065x; 1.4251x over previous
#include <cuda_runtime.h>
#include <cuda_bf16.h>
#include <math_constants.h>
#include <cstdint>

// Problem constants
#define B   2
#define NP  8192
#define C   64
#define M   4096
#define K   128
#define H   128
#define R2  0.04f
#define BM  (B*M)
#define NPAD 136        // padded row length (bf16 elems); 272B stride -> conflict-free ldmatrix

// ---------------- scratch ----------------
__device__ int   g_flags[B*NP];
__device__ int   g_sidx[BM];
__device__ float g_Y[(size_t)B*NP*H];
__device__ int   g_nbr[(size_t)BM*K];
__device__ int   g_ncnt[BM];
__device__ __nv_bfloat16 g_w2t_h[H*NPAD];   // W2^T hi, padded rows
__device__ __nv_bfloat16 g_w2t_l[H*NPAD];   // W2^T lo

// ---------------- helpers ----------------
__device__ __forceinline__ uint32_t smem_u32(const void* p) {
    uint32_t a;
    asm("{ .reg .u64 t; cvta.to.shared.u64 t, %1; cvt.u32.u64 %0, t; }" : "=r"(a) : "l"(p));
    return a;
}
__device__ __forceinline__ unsigned long long pack2f(float lo, float hi) {
    unsigned long long r;
    asm("mov.b64 %0, {%1, %2};" : "=l"(r) : "f"(lo), "f"(hi));
    return r;
}
__device__ __forceinline__ unsigned long long fma2(unsigned long long a,
                                                   unsigned long long b,
                                                   unsigned long long c) {
    unsigned long long d;
    asm("fma.rn.f32x2 %0, %1, %2, %3;" : "=l"(d) : "l"(a), "l"(b), "l"(c));
    return d;
}
__device__ __forceinline__ float2 unpack2f(unsigned long long v) {
    float lo, hi;
    asm("mov.b64 {%0, %1}, %2;" : "=f"(lo), "=f"(hi) : "l"(v));
    return make_float2(lo, hi);
}
__device__ __forceinline__ void ldm_x4(uint32_t* r, uint32_t addr) {
    asm volatile("ldmatrix.sync.aligned.m8n8.x4.shared.b16 {%0,%1,%2,%3}, [%4];"
                 : "=r"(r[0]), "=r"(r[1]), "=r"(r[2]), "=r"(r[3]) : "r"(addr));
}
__device__ __forceinline__ void ldm_x2(uint32_t* r, uint32_t addr) {
    asm volatile("ldmatrix.sync.aligned.m8n8.x2.shared.b16 {%0,%1}, [%2];"
                 : "=r"(r[0]), "=r"(r[1]) : "r"(addr));
}
__device__ __forceinline__ void mma_bf16(float* d, const uint32_t* a, const uint32_t* bq) {
    asm volatile(
        "mma.sync.aligned.m16n8k16.row.col.f32.bf16.bf16.f32 "
        "{%0,%1,%2,%3}, {%4,%5,%6,%7}, {%8,%9}, {%0,%1,%2,%3};"
        : "+f"(d[0]), "+f"(d[1]), "+f"(d[2]), "+f"(d[3])
        : "r"(a[0]), "r"(a[1]), "r"(a[2]), "r"(a[3]), "r"(bq[0]), "r"(bq[1]));
}

// ---------------- K0: zero flags ----------------
__global__ void zero_flags_kernel() {
    int i = blockIdx.x * blockDim.x + threadIdx.x;
    if (i < B*NP) g_flags[i] = 0;
}

// ---------------- K1: FPS (R6 proven config) ----------------
#define T_FPS 512
#define PTS   (NP / T_FPS)
#define PRS   (PTS / 2)
#define NW    (T_FPS / 32)

__global__ void __launch_bounds__(T_FPS, 1)
fps_kernel(const float* __restrict__ pos) {
    const int b   = blockIdx.x;
    const int tid = threadIdx.x;
    const int lane = tid & 31, wid = tid >> 5;

    extern __shared__ float4 sp[];
    __shared__ unsigned long long s_vi[2][NW];

    const float* pb = pos + (size_t)b * NP * 3;
    for (int i = tid; i < NP; i += T_FPS)
        sp[i] = make_float4(pb[i*3+0], pb[i*3+1], pb[i*3+2], 0.0f);
    if (tid == 0) g_flags[b*NP + 0] = 1;
    __syncthreads();

    unsigned long long px2[PRS], py2[PRS], pz2[PRS];
    float mind[PTS];
    const int base = tid * PTS;
    #pragma unroll
    for (int k = 0; k < PRS; k++) {
        float4 a = sp[base + 2*k], q = sp[base + 2*k + 1];
        px2[k] = pack2f(a.x, q.x);
        py2[k] = pack2f(a.y, q.y);
        pz2[k] = pack2f(a.z, q.z);
    }
    #pragma unroll
    for (int k = 0; k < PTS; k++) mind[k] = CUDART_INF_F;

    float4 w0 = sp[0];
    float fx = w0.x, fy = w0.y, fz = w0.z;

    for (int it = 1; it < M; it++) {
        const int cur = it & 1;
        const unsigned long long nfx2 = pack2f(-fx, -fx);
        const unsigned long long nfy2 = pack2f(-fy, -fy);
        const unsigned long long nfz2 = pack2f(-fz, -fz);
        float bv = 0.0f; int bloc = 0;
        #pragma unroll
        for (int k = 0; k < PRS; k++) {
            unsigned long long dx, dy, dz;
            asm("add.rn.f32x2 %0, %1, %2;" : "=l"(dx) : "l"(px2[k]), "l"(nfx2));
            asm("add.rn.f32x2 %0, %1, %2;" : "=l"(dy) : "l"(py2[k]), "l"(nfy2));
            asm("add.rn.f32x2 %0, %1, %2;" : "=l"(dz) : "l"(pz2[k]), "l"(nfz2));
            unsigned long long d;
            asm("mul.rn.f32x2 %0, %1, %2;" : "=l"(d) : "l"(dz), "l"(dz));
            d = fma2(dy, dy, d);
            d = fma2(dx, dx, d);
            float2 df = unpack2f(d);
            float m0 = fminf(mind[2*k+0], df.x); mind[2*k+0] = m0;
            float m1 = fminf(mind[2*k+1], df.y); mind[2*k+1] = m1;
            if (m0 > bv) { bv = m0; bloc = base + 2*k;     }
            if (m1 > bv) { bv = m1; bloc = base + 2*k + 1; }
        }
        const unsigned bvu  = __float_as_uint(bv);
        const unsigned wmax = __reduce_max_sync(0xffffffffu, bvu);
        const int cand = (bvu == wmax) ? bloc : 0x7fffffff;
        const int wloc = __reduce_min_sync(0xffffffffu, cand);
        if (lane == 0)
            s_vi[cur][wid] = ((unsigned long long)wmax << 32) | (unsigned)wloc;
        __syncthreads();

        const unsigned long long pv = s_vi[cur][lane & (NW-1)];
        const unsigned hv = (unsigned)(pv >> 32);
        const unsigned g  = __reduce_max_sync(0xffffffffu, hv);
        const int ic   = (hv == g) ? (int)(unsigned)pv : 0x7fffffff;
        const int widx = __reduce_min_sync(0xffffffffu, ic);

        const float4 w = sp[widx];
        fx = w.x; fy = w.y; fz = w.z;
        if (tid == 0) g_flags[b*NP + widx] = 1;
    }
}

// ---------------- K2: compaction ----------------
__global__ void compact_kernel() {
    const int b = blockIdx.x, lane = threadIdx.x;
    int carry = 0;
    for (int base = 0; base < NP; base += 32) {
        int f = g_flags[b*NP + base + lane];
        unsigned m = __ballot_sync(0xffffffffu, f);
        if (f) {
            int r = __popc(m & ((1u << lane) - 1u));
            g_sidx[b*M + carry + r] = base + lane;
        }
        carry += __popc(m);
    }
}

// ---------------- K3: Y = x @ W1[:C] + b1 ----------------
__global__ void ymat_kernel(const float* __restrict__ x,
                            const float* __restrict__ W1,
                            const float* __restrict__ b1) {
    const int p = blockIdx.x;
    const int h = threadIdx.x;
    __shared__ float xv[C];
    if (h < C) xv[h] = x[(size_t)p*C + h];
    __syncthreads();
    float acc = b1[h];
    #pragma unroll
    for (int c = 0; c < C; c++)
        acc = fmaf(xv[c], W1[c*H + h], acc);
    g_Y[(size_t)p*H + h] = acc;
}

// ---------------- K4: radius / top-K ----------------
#define CAP 2048
__global__ void radius_kernel(const float* __restrict__ pos) {
    const int ctr = blockIdx.x;
    const int b   = ctr / M;
    const int ci  = g_sidx[ctr];
    const float* pb = pos + (size_t)b * NP * 3;
    const float cx = pb[ci*3+0], cy = pb[ci*3+1], cz = pb[ci*3+2];

    __shared__ float cd[CAP];
    __shared__ int   cidx[CAP];
    __shared__ int   cnt;
    if (threadIdx.x == 0) cnt = 0;
    __syncthreads();

    for (int i = threadIdx.x; i < NP; i += 256) {
        float dx = pb[i*3+0] - cx, dy = pb[i*3+1] - cy, dz = pb[i*3+2] - cz;
        float d  = fmaf(dx, dx, fmaf(dy, dy, dz*dz));
        if (d <= R2) {
            int s = atomicAdd(&cnt, 1);
            if (s < CAP) { cd[s] = d; cidx[s] = i; }
        }
    }
    __syncthreads();
    int n = min(cnt, CAP);
    if (n <= K) {
        for (int c = threadIdx.x; c < n; c += 256)
            g_nbr[(size_t)ctr*K + c] = cidx[c];
        if (threadIdx.x == 0) g_ncnt[ctr] = n;
    } else {
        for (int c = threadIdx.x; c < n; c += 256) {
            float d = cd[c]; int id = cidx[c];
            int r = 0;
            for (int j = 0; j < n; j++) {
                float dj = cd[j];
                r += (dj < d) || (dj == d && cidx[j] < id);
            }
            if (r < K) g_nbr[(size_t)ctr*K + r] = id;
        }
        if (threadIdx.x == 0) g_ncnt[ctr] = K;
    }
}

// ---------------- K4b: W2 split/transpose into padded rows ----------------
__global__ void w2prep_kernel(const float* __restrict__ W2) {
    int i = blockIdx.x * blockDim.x + threadIdx.x;
    if (i >= H * H) return;
    int k = i / H, o = i % H;              // W2[k][o]
    float w = W2[k*H + o];
    __nv_bfloat16 wh = __float2bfloat16(w);
    __nv_bfloat16 wl = __float2bfloat16(w - __bfloat162float(wh));
    g_w2t_h[o*NPAD + k] = wh;              // row o = output channel, col k
    g_w2t_l[o*NPAD + k] = wl;
}

// ---------------- K5: PointNetConv via mma.sync bf16-split ----------------
#define TILE_B  (H * NPAD * 2)         // 34816 bytes per tile
#define SM_H1H  0
#define SM_H1L  (TILE_B)
#define SM_W2H  (2*TILE_B)
#define SM_W2L  (3*TILE_B)
#define SM_B2   (4*TILE_B)
#define SM_TOT  (4*TILE_B + 512)

__global__ void __launch_bounds__(128, 1)
conv_mma_kernel(const float* __restrict__ pos,
                const float* __restrict__ W1,
                const float* __restrict__ b2,
                float* __restrict__ out) {     // grid = BM, block = 128
    extern __shared__ char sm[];
    const uint32_t smb = smem_u32(sm);
    const int ctr = blockIdx.x;
    const int b   = ctr / M;
    const int tid = threadIdx.x;
    const int w   = tid >> 5, lane = tid & 31;

    // copy W2 tiles + b2
    {
        const uint4* srcH = (const uint4*)g_w2t_h;
        const uint4* srcL = (const uint4*)g_w2t_l;
        uint4* dstH = (uint4*)(sm + SM_W2H);
        uint4* dstL = (uint4*)(sm + SM_W2L);
        for (int i = tid; i < TILE_B/16; i += 128) { dstH[i] = srcH[i]; dstL[i] = srcL[i]; }
        if (tid < H) ((float*)(sm + SM_B2))[tid] = b2[tid];
    }

    // build h1 row (bf16 split) into smem
    const int n = g_ncnt[ctr];
    const int ci = g_sidx[ctr];
    const float* pb = pos + (size_t)b * NP * 3;
    const float cx = pb[ci*3+0], cy = pb[ci*3+1], cz = pb[ci*3+2];

    const int row = tid;
    const bool rvalid = (row < n);
    {
        uint32_t* h1h = (uint32_t*)(sm + SM_H1H) + row * (NPAD/2);
        uint32_t* h1l = (uint32_t*)(sm + SM_H1L) + row * (NPAD/2);
        if (rvalid) {
            int j = g_nbr[(size_t)ctr*K + row];
            const float* yrow = g_Y + (size_t)(b*NP + j) * H;
            float relx = pb[j*3+0] - cx, rely = pb[j*3+1] - cy, relz = pb[j*3+2] - cz;
            #pragma unroll
            for (int q = 0; q < H/2; q++) {
                int i0 = 2*q;
                float h0  = yrow[i0]   + relx*W1[(C+0)*H + i0]   + rely*W1[(C+1)*H + i0]   + relz*W1[(C+2)*H + i0];
                float h1v = yrow[i0+1] + relx*W1[(C+0)*H + i0+1] + rely*W1[(C+1)*H + i0+1] + relz*W1[(C+2)*H + i0+1];
                h0 = fmaxf(h0, 0.0f); h1v = fmaxf(h1v, 0.0f);
                __nv_bfloat16 b0 = __float2bfloat16(h0);
                __nv_bfloat16 b1 = __float2bfloat16(h1v);
                __nv_bfloat16 l0 = __float2bfloat16(h0  - __bfloat162float(b0));
                __nv_bfloat16 l1 = __float2bfloat16(h1v - __bfloat162float(b1));
                h1h[q] = (uint32_t)__bfloat16_as_ushort(b0) | ((uint32_t)__bfloat16_as_ushort(b1) << 16);
                h1l[q] = (uint32_t)__bfloat16_as_ushort(l0) | ((uint32_t)__bfloat16_as_ushort(l1) << 16);
            }
        } else {
            #pragma unroll
            for (int q = 0; q < H/2; q++) { h1h[q] = 0u; h1l[q] = 0u; }
        }
    }
    __syncthreads();

    // ---- GEMM: D = Ah*Bh + Ah*Bl + Al*Bh, fp32 accum ----
    float acc[2][16][4];
    #pragma unroll
    for (int m2 = 0; m2 < 2; m2++)
        #pragma unroll
        for (int nn = 0; nn < 16; nn++)
            #pragma unroll
            for (int j = 0; j < 4; j++) acc[m2][nn][j] = 0.0f;

    const uint32_t abase_arr[3] = { smb + SM_H1H, smb + SM_H1H, smb + SM_H1L };
    const uint32_t bbase_arr[3] = { smb + SM_W2H, smb + SM_W2L, smb + SM_W2H };
    const uint32_t arow = (uint32_t)(lane & 15);
    const uint32_t acol = (uint32_t)((lane >> 4) * 8);
    const uint32_t bln  = (uint32_t)(lane & 7);
    const uint32_t bhalf= (uint32_t)((lane >> 3) & 1) * 8;

    for (int pass = 0; pass < 3; pass++) {
        const uint32_t abase = abase_arr[pass];
        const uint32_t bbase = bbase_arr[pass];
        for (int k8 = 0; k8 < 8; k8++) {
            const uint32_t kb = (uint32_t)k8 * 16;
            uint32_t a0[4], a1[4];
            ldm_x4(a0, abase + (((uint32_t)(32*w)      + arow) * NPAD + kb + acol) * 2);
            ldm_x4(a1, abase + (((uint32_t)(32*w + 16) + arow) * NPAD + kb + acol) * 2);
            #pragma unroll
            for (int nn = 0; nn < 16; nn++) {
                uint32_t bq[2];
                // non-trans: W2^T rows are n, cols are k (k contiguous) -> fragment
                // {B[k=2q][n], B[k=2q+1][n]} with n = lane/4, halves split by k+8.
                ldm_x2(bq, bbase + (((uint32_t)(nn*8) + bln) * NPAD + kb + bhalf) * 2);
                mma_bf16(acc[0][nn], a0, bq);
                mma_bf16(acc[1][nn], a1, bq);
            }
        }
    }
    __syncthreads();   // everyone done reading h1 before aliasing writes

    // ---- epilogue: bias+relu+row-mask -> transposed smem -> column max ----
    float* vals = (float*)sm;                       // [128][129], aliases h1
    const float* b2s = (const float*)(sm + SM_B2);
    const int gid = lane >> 2, tig = lane & 3;
    #pragma unroll
    for (int m2 = 0; m2 < 2; m2++) {
        const int r0 = 32*w + 16*m2 + gid;
        const int r1 = r0 + 8;
        const bool v0 = (r0 < n), v1 = (r1 < n);
        #pragma unroll
        for (int nn = 0; nn < 16; nn++) {
            const int col = nn*8 + tig*2;
            const float bi0 = b2s[col], bi1 = b2s[col+1];
            vals[r0*129 + col]     = v0 ? fmaxf(acc[m2][nn][0] + bi0, 0.0f) : 0.0f;
            vals[r0*129 + col + 1] = v0 ? fmaxf(acc[m2][nn][1] + bi1, 0.0f) : 0.0f;
            vals[r1*129 + col]     = v1 ? fmaxf(acc[m2][nn][2] + bi0, 0.0f) : 0.0f;
            vals[r1*129 + col + 1] = v1 ? fmaxf(acc[m2][nn][3] + bi1, 0.0f) : 0.0f;
        }
    }
    __syncthreads();

    float mx = 0.0f;
    #pragma unroll 8
    for (int r = 0; r < 128; r++)
        mx = fmaxf(mx, vals[r*129 + tid]);
    out[(size_t)ctr*H + tid] = mx;
}

// ---------------- K6: pack auxiliary outputs ----------------
__global__ void pack_kernel(const float* __restrict__ pos, float* __restrict__ out,
                            int out_size) {
    const int i = blockIdx.x * blockDim.x + threadIdx.x;
    if (i >= BM) return;
    const int b  = i / M;
    const int ci = g_sidx[i];
    const float* pb = pos + (size_t)b * NP * 3;
    const int base_q = BM * H;
    if (out_size >= base_q + BM*3) {
        out[base_q + i*3 + 0] = pb[ci*3+0];
        out[base_q + i*3 + 1] = pb[ci*3+1];
        out[base_q + i*3 + 2] = pb[ci*3+2];
    }
    const int base_b = base_q + BM*3;
    if (out_size >= base_b + BM) {
        out[base_b + i] = (float)b;
    }
}

// ---------------- launch ----------------
extern "C" void kernel_launch(void* const* d_in, const int* in_sizes, int n_in,
                              void* d_out, int out_size) {
    const float* x    = (const float*)d_in[0];
    const float* pos  = (const float*)d_in[1];
    const float* W1   = (const float*)d_in[3];
    const float* b1   = (const float*)d_in[4];
    const float* W2   = (const float*)d_in[5];
    const float* b2   = (const float*)d_in[6];
    float* out = (float*)d_out;

    const int fps_smem = NP * (int)sizeof(float4);
    cudaFuncSetAttribute(fps_kernel, cudaFuncAttributeMaxDynamicSharedMemorySize, fps_smem);
    cudaFuncSetAttribute(conv_mma_kernel, cudaFuncAttributeMaxDynamicSharedMemorySize, SM_TOT);

    zero_flags_kernel<<<(B*NP + 255)/256, 256>>>();
    ymat_kernel<<<B*NP, H>>>(x, W1, b1);
    w2prep_kernel<<<(H*H + 127)/128, 128>>>(W2);
    fps_kernel<<<B, T_FPS, fps_smem>>>(pos);
    compact_kernel<<<B, 32>>>();
    radius_kernel<<<BM, 256>>>(pos);
    conv_mma_kernel<<<BM, 128, SM_TOT>>>(pos, W1, b2, out);
    pack_kernel<<<(BM + 255)/256, 256>>>(pos, out, out_size);
}